// round 16
// baseline (speedup 1.0000x reference)
#include <cuda_runtime.h>
#include <cuda_fp16.h>
#include <cstdint>

// Problem constants (fixed by the dataset)
#define NN 100000        // nodes
#define NE 3200000       // edges
#define DF 128           // input feat
#define NH1 128          // layer1 out
#define NH2 64           // layer2 out
#define NG 256           // graphs
#define NC 10            // classes

#define SCAN_B 1024
#define SCAN_NB ((NN + SCAN_B - 1) / SCAN_B)   // 98

// ---------------- scratch (static device memory; no allocation) -------------
// Invariants across calls: g_cnt == 0 on entry; g_blocksum == 0 on entry.
__device__ int   g_is64;               // 1 if indices are int64, 0 if int32
__device__ float g_dis[NN];            // deg^-1/2
__device__ int   g_cnt[NN];            // per-dst edge count
__device__ int   g_rowptr[NN + 1];     // CSR row pointers
__device__ int   g_woff[NN];           // scatter write offsets
__device__ int   g_blocksum[SCAN_NB];  // flagged block sums (value+1)
__device__ int   g_csr_src[NE];        // CSR column (src) indices
__device__ __align__(16) uint4 g_h1h[NN * 16];    // (x @ W1)*dis, fp16, 128 h/row
__device__ __align__(16) uint4 g_r1h[NN * 16];    // relu(gcn1), fp16
__device__ __align__(16) uint4 g_h2h[NN * 8];     // (r1 @ W2)*dis, fp16, 64 h/row
__device__ float g_pool[NG * NH2];     // graph sums
__device__ float g_pcnt[NG];           // graph node counts

// index load helper: p holds either int32 or int64 elements
__device__ __forceinline__ int ld_idx(const void* p, long long i, int is64) {
    if (is64) return (int)((const long long*)p)[i];
    return ((const int*)p)[i];
}

// ---------------- hist (+ dtype detect) ----------------------------------------

__global__ void k_hist(const void* __restrict__ ei) {
    __shared__ int nz;
    if (threadIdx.x == 0) nz = 0;
    __syncthreads();
    if (threadIdx.x < 256) {
        if (((const int*)ei)[2 * threadIdx.x + 1] != 0) atomicOr(&nz, 1);
    }
    __syncthreads();
    int is64 = (nz == 0);
    if (blockIdx.x == 0 && threadIdx.x == 0) g_is64 = is64;
    int e = blockIdx.x * blockDim.x + threadIdx.x;
    if (e < NE) {
        int d = ld_idx(ei, (long long)NE + e, is64);
        atomicAdd(&g_cnt[d], 1);
    }
}

// ---------------- single-pass scan (decoupled lookback) ------------------------
__global__ void k_scan() {
    __shared__ int s[SCAN_B];
    __shared__ int pre[SCAN_NB];
    int t = threadIdx.x, b = blockIdx.x;
    int i = b * SCAN_B + t;
    int v = 0;
    if (i < NN) {
        v = g_cnt[i];
        g_cnt[i] = 0;                       // re-establish invariant for next call
        g_dis[i] = rsqrtf((float)v + 1.0f);
    }
    s[t] = v;
    __syncthreads();
    #pragma unroll
    for (int off = 1; off < SCAN_B; off <<= 1) {
        int add = (t >= off) ? s[t - off] : 0;
        __syncthreads();
        s[t] += add;
        __syncthreads();
    }
    int incl = s[t];
    if (t == SCAN_B - 1) {
        __threadfence();
        atomicExch(&g_blocksum[b], incl + 1);
    }
    if (b == 0) {
        for (int j = t; j < NG * NH2; j += SCAN_B) g_pool[j] = 0.f;
        if (t < NG) g_pcnt[t] = 0.f;
    }
    if (t < b) {
        volatile int* bs = g_blocksum;
        int x;
        do { x = bs[t]; } while (x == 0);
        pre[t] = x - 1;
    }
    __syncthreads();
    __shared__ int prefix;
    if (t == 0) {
        int p = 0;
        for (int j = 0; j < b; j++) p += pre[j];
        prefix = p;
    }
    __syncthreads();
    if (i < NN) {
        int excl = prefix + incl - v;
        g_rowptr[i] = excl;
        g_woff[i] = excl;
    }
    if (i == 0) g_rowptr[NN] = NE;
}

// ---------------- scatter -------------------------------------------------------

__global__ void k_scatter(const void* __restrict__ ei) {
    if (blockIdx.x == 0 && threadIdx.x < SCAN_NB) g_blocksum[threadIdx.x] = 0;
    int e = blockIdx.x * blockDim.x + threadIdx.x;
    int is64 = g_is64;
    if (e < NE) {
        int s = ld_idx(ei, e, is64);
        int d = ld_idx(ei, (long long)NE + e, is64);
        int pos = atomicAdd(&g_woff[d], 1);
        g_csr_src[pos] = s;
    }
}

// ---------------- tensor-core GEMM (mma.sync m16n8k16 fp16 -> fp32) ----------
// Optional epilogue scale: C[row,:] *= g_dis[row]  (folds GCN norm into features)
__device__ __forceinline__ uint4 cvt8(const float* p) {
    const float4* s = (const float4*)p;
    float4 f0 = s[0], f1 = s[1];
    uint4 v;
    *(__half2*)&v.x = __floats2half2_rn(f0.x, f0.y);
    *(__half2*)&v.y = __floats2half2_rn(f0.z, f0.w);
    *(__half2*)&v.z = __floats2half2_rn(f1.x, f1.y);
    *(__half2*)&v.w = __floats2half2_rn(f1.z, f1.w);
    return v;
}
__device__ __forceinline__ uint4 ld_chunk(const __half* A, long long row, int ch) {
    return ((const uint4*)A)[row * 16 + ch];
}
__device__ __forceinline__ uint4 ld_chunk(const float* A, long long row, int ch) {
    return cvt8(&A[row * 128 + ch * 8]);
}
__device__ __forceinline__ uint4 ld_wchunk(const __half* W, int c) {
    return ((const uint4*)W)[c];
}
__device__ __forceinline__ uint4 ld_wchunk(const float* W, int c) {
    return cvt8(&W[c * 8]);
}

template <int NOUT, bool SCALE, typename AT, typename WT>
__global__ void k_gemm_mma(const AT* __restrict__ A, const WT* __restrict__ W,
                           __half2* __restrict__ C, int M) {
    constexpr int K = 128;
    constexpr int AST = 136;
    constexpr int WST = NOUT + 8;
    extern __shared__ __half sm[];
    __half* As = sm;
    __half* Ws = sm + 128 * AST;
    int tid = threadIdx.x;
    int wid = tid >> 5, lane = tid & 31;
    int rb = blockIdx.x * 128;

    #pragma unroll
    for (int i = 0; i < 8; i++) {
        int c = tid + i * 256;
        int row = c >> 4, ch = c & 15;
        int gr = rb + row;
        uint4 v = make_uint4(0u, 0u, 0u, 0u);
        if (gr < M) v = ld_chunk(A, (long long)gr, ch);
        *(uint4*)&As[row * AST + ch * 8] = v;
    }
    {
        constexpr int NCH = K * NOUT / 8;
        #pragma unroll
        for (int c = tid; c < NCH; c += 256) {
            int row = c / (NOUT / 8), col = c % (NOUT / 8);
            *(uint4*)&Ws[row * WST + col * 8] = ld_wchunk(W, c);
        }
    }
    __syncthreads();

    constexpr int NT = NOUT / 8;
    float acc[NT][4];
    #pragma unroll
    for (int i = 0; i < NT; i++) {
        acc[i][0] = acc[i][1] = acc[i][2] = acc[i][3] = 0.f;
    }

    uint32_t a_base = (uint32_t)__cvta_generic_to_shared(
                          &As[(wid * 16 + (lane & 15)) * AST]) + ((lane >> 4) << 4);
    uint32_t b_base = (uint32_t)__cvta_generic_to_shared(
                          &Ws[(lane & 15) * WST]) + ((lane >> 4) << 4);

    #pragma unroll
    for (int kk = 0; kk < K / 16; kk++) {
        uint32_t a0, a1, a2, a3;
        asm volatile("ldmatrix.sync.aligned.m8n8.x4.shared.b16 {%0,%1,%2,%3}, [%4];"
                     : "=r"(a0), "=r"(a1), "=r"(a2), "=r"(a3)
                     : "r"(a_base + kk * 32));
        uint32_t brow = b_base + kk * 16 * (WST * 2);
        #pragma unroll
        for (int n2 = 0; n2 < NOUT / 16; n2++) {
            uint32_t b0, b1, b2, b3;
            asm volatile("ldmatrix.sync.aligned.m8n8.x4.trans.shared.b16 {%0,%1,%2,%3}, [%4];"
                         : "=r"(b0), "=r"(b1), "=r"(b2), "=r"(b3)
                         : "r"(brow + n2 * 32));
            asm volatile("mma.sync.aligned.m16n8k16.row.col.f32.f16.f16.f32 "
                         "{%0,%1,%2,%3}, {%4,%5,%6,%7}, {%8,%9}, {%0,%1,%2,%3};"
                         : "+f"(acc[2*n2][0]), "+f"(acc[2*n2][1]),
                           "+f"(acc[2*n2][2]), "+f"(acc[2*n2][3])
                         : "r"(a0), "r"(a1), "r"(a2), "r"(a3), "r"(b0), "r"(b1));
            asm volatile("mma.sync.aligned.m16n8k16.row.col.f32.f16.f16.f32 "
                         "{%0,%1,%2,%3}, {%4,%5,%6,%7}, {%8,%9}, {%0,%1,%2,%3};"
                         : "+f"(acc[2*n2+1][0]), "+f"(acc[2*n2+1][1]),
                           "+f"(acc[2*n2+1][2]), "+f"(acc[2*n2+1][3])
                         : "r"(a0), "r"(a1), "r"(a2), "r"(a3), "r"(b2), "r"(b3));
        }
    }

    int r0 = rb + wid * 16 + (lane >> 2);
    int cq = lane & 3;
    bool w0 = r0 < M, w1 = (r0 + 8) < M;
    float sc0 = 1.f, sc1 = 1.f;
    if (SCALE) {
        if (w0) sc0 = g_dis[r0];
        if (w1) sc1 = g_dis[r0 + 8];
    }
    #pragma unroll
    for (int nt = 0; nt < NT; nt++) {
        if (w0) C[(long long)r0 * (NOUT/2) + nt * 4 + cq] =
                    __floats2half2_rn(acc[nt][0] * sc0, acc[nt][1] * sc0);
        if (w1) C[(long long)(r0 + 8) * (NOUT/2) + nt * 4 + cq] =
                    __floats2half2_rn(acc[nt][2] * sc1, acc[nt][3] * sc1);
    }
}

// ---------------- aggregation kernels ------------------------------------------
// Multi-edge-per-warp, weight-free gathers. agg1: 2 edges/warp-instruction
// (half-warp x uint4 covers a 256B row). agg2: 4 edges (8 lanes x uint4 = 128B).
// fp16 group accumulation (flush every 8 edges), fp32 totals, shfl_xor combine.

__global__ void k_agg1(const float* __restrict__ b1) {
    int gw   = (blockIdx.x * blockDim.x + threadIdx.x) >> 5;
    int lane = threadIdx.x & 31;
    if (gw >= NN) return;
    int d    = gw;
    int half = lane >> 4;          // which edge of the pair
    int ll   = lane & 15;          // 16B chunk within the 256B row
    int s0 = g_rowptr[d], s1 = g_rowptr[d + 1];
    float acc[8] = {0.f,0.f,0.f,0.f,0.f,0.f,0.f,0.f};
    const __half2 hz = __float2half2_rn(0.f);
    for (int j0 = s0; j0 < s1; j0 += 32) {
        int jj = j0 + lane;
        int s_l = (jj < s1) ? g_csr_src[jj] : 0;
        int m = min(32, s1 - j0);
        int k = 0;
        while (k < m) {
            int kend = min(k + 8, m);
            __half2 h0 = hz, h1 = hz, h2 = hz, h3 = hz;
            for (; k < kend; k += 2) {
                int idx = k + half;
                int s = __shfl_sync(0xffffffffu, s_l, idx);
                if (idx < m) {
                    uint4 raw = g_h1h[(long long)s * 16 + ll];
                    h0 = __hadd2(h0, *(__half2*)&raw.x);
                    h1 = __hadd2(h1, *(__half2*)&raw.y);
                    h2 = __hadd2(h2, *(__half2*)&raw.z);
                    h3 = __hadd2(h3, *(__half2*)&raw.w);
                }
            }
            float2 f;
            f = __half22float2(h0); acc[0] += f.x; acc[1] += f.y;
            f = __half22float2(h1); acc[2] += f.x; acc[3] += f.y;
            f = __half22float2(h2); acc[4] += f.x; acc[5] += f.y;
            f = __half22float2(h3); acc[6] += f.x; acc[7] += f.y;
        }
    }
    // combine the two half-warp partials (same feature chunk ll)
    #pragma unroll
    for (int i = 0; i < 8; i++)
        acc[i] += __shfl_xor_sync(0xffffffffu, acc[i], 16);
    if (half == 0) {
        float dd = g_dis[d];
        uint4 hraw = g_h1h[(long long)d * 16 + ll];     // self row (already *dis)
        float2 s0f = __half22float2(*(__half2*)&hraw.x);
        float2 s1f = __half22float2(*(__half2*)&hraw.y);
        float2 s2f = __half22float2(*(__half2*)&hraw.z);
        float2 s3f = __half22float2(*(__half2*)&hraw.w);
        const float4* b4 = (const float4*)b1;
        float4 ba = b4[ll * 2], bb = b4[ll * 2 + 1];
        float o0 = fmaxf(dd * (acc[0] + s0f.x) + ba.x, 0.f);
        float o1 = fmaxf(dd * (acc[1] + s0f.y) + ba.y, 0.f);
        float o2 = fmaxf(dd * (acc[2] + s1f.x) + ba.z, 0.f);
        float o3 = fmaxf(dd * (acc[3] + s1f.y) + ba.w, 0.f);
        float o4 = fmaxf(dd * (acc[4] + s2f.x) + bb.x, 0.f);
        float o5 = fmaxf(dd * (acc[5] + s2f.y) + bb.y, 0.f);
        float o6 = fmaxf(dd * (acc[6] + s3f.x) + bb.z, 0.f);
        float o7 = fmaxf(dd * (acc[7] + s3f.y) + bb.w, 0.f);
        uint4 o;
        *(__half2*)&o.x = __floats2half2_rn(o0, o1);
        *(__half2*)&o.y = __floats2half2_rn(o2, o3);
        *(__half2*)&o.z = __floats2half2_rn(o4, o5);
        *(__half2*)&o.w = __floats2half2_rn(o6, o7);
        g_r1h[(long long)d * 16 + ll] = o;
    }
}

__global__ void k_agg2_pool(const float* __restrict__ b2,
                            const void* __restrict__ batch) {
    int gw   = (blockIdx.x * blockDim.x + threadIdx.x) >> 5;
    int lane = threadIdx.x & 31;
    if (gw >= NN) return;
    int is64 = g_is64;
    int d  = gw;
    int q  = lane >> 3;            // which edge of the quad
    int ll = lane & 7;             // 16B chunk within the 128B row
    int s0 = g_rowptr[d], s1 = g_rowptr[d + 1];
    float acc[8] = {0.f,0.f,0.f,0.f,0.f,0.f,0.f,0.f};
    const __half2 hz = __float2half2_rn(0.f);
    for (int j0 = s0; j0 < s1; j0 += 32) {
        int jj = j0 + lane;
        int s_l = (jj < s1) ? g_csr_src[jj] : 0;
        int m = min(32, s1 - j0);
        int k = 0;
        while (k < m) {
            int kend = min(k + 8, m);
            __half2 h0 = hz, h1 = hz, h2 = hz, h3 = hz;
            for (; k < kend; k += 4) {
                int idx = k + q;
                int s = __shfl_sync(0xffffffffu, s_l, idx & 31);
                if (idx < m) {
                    uint4 raw = g_h2h[(long long)s * 8 + ll];
                    h0 = __hadd2(h0, *(__half2*)&raw.x);
                    h1 = __hadd2(h1, *(__half2*)&raw.y);
                    h2 = __hadd2(h2, *(__half2*)&raw.z);
                    h3 = __hadd2(h3, *(__half2*)&raw.w);
                }
            }
            float2 f;
            f = __half22float2(h0); acc[0] += f.x; acc[1] += f.y;
            f = __half22float2(h1); acc[2] += f.x; acc[3] += f.y;
            f = __half22float2(h2); acc[4] += f.x; acc[5] += f.y;
            f = __half22float2(h3); acc[6] += f.x; acc[7] += f.y;
        }
    }
    // combine quads: xor 8 then 16
    #pragma unroll
    for (int i = 0; i < 8; i++) {
        acc[i] += __shfl_xor_sync(0xffffffffu, acc[i], 8);
        acc[i] += __shfl_xor_sync(0xffffffffu, acc[i], 16);
    }
    if (q == 0) {
        float dd = g_dis[d];
        uint4 hraw = g_h2h[(long long)d * 8 + ll];      // self row (already *dis)
        float2 s0f = __half22float2(*(__half2*)&hraw.x);
        float2 s1f = __half22float2(*(__half2*)&hraw.y);
        float2 s2f = __half22float2(*(__half2*)&hraw.z);
        float2 s3f = __half22float2(*(__half2*)&hraw.w);
        const float4* b4 = (const float4*)b2;
        float4 ba = b4[ll * 2], bb = b4[ll * 2 + 1];
        float o[8];
        o[0] = dd * (acc[0] + s0f.x) + ba.x;
        o[1] = dd * (acc[1] + s0f.y) + ba.y;
        o[2] = dd * (acc[2] + s1f.x) + ba.z;
        o[3] = dd * (acc[3] + s1f.y) + ba.w;
        o[4] = dd * (acc[4] + s2f.x) + bb.x;
        o[5] = dd * (acc[5] + s2f.y) + bb.y;
        o[6] = dd * (acc[6] + s3f.x) + bb.z;
        o[7] = dd * (acc[7] + s3f.y) + bb.w;
        int g = ld_idx(batch, d, is64);
        float* pp = &g_pool[g * NH2 + ll * 8];
        #pragma unroll
        for (int i = 0; i < 8; i++) atomicAdd(pp + i, o[i]);
        if (ll == 0) atomicAdd(&g_pcnt[g], 1.0f);
    }
}

__global__ void k_final(const float* __restrict__ Wfc,
                        const float* __restrict__ bfc,
                        float* __restrict__ out) {
    int g = blockIdx.x;
    int c = threadIdx.x;
    if (c >= NC) return;
    float inv = 1.0f / fmaxf(g_pcnt[g], 1.0f);
    float s = 0.f;
    #pragma unroll 8
    for (int f = 0; f < NH2; f++) {
        s += g_pool[g * NH2 + f] * Wfc[f * NC + c];
    }
    out[g * NC + c] = s * inv + bfc[c];
}

// ---------------- launch -----------------------------------------------------

extern "C" void kernel_launch(void* const* d_in, const int* in_sizes, int n_in,
                              void* d_out, int out_size) {
    const float* x     = (const float*)d_in[0];
    const void*  ei    = d_in[1];
    const void*  batch = d_in[2];
    const float* W1    = (const float*)d_in[3];
    const float* b1    = (const float*)d_in[4];
    const float* W2    = (const float*)d_in[5];
    const float* b2    = (const float*)d_in[6];
    const float* Wfc   = (const float*)d_in[7];
    const float* bfc   = (const float*)d_in[8];
    float* out = (float*)d_out;

    const int TB = 256;
    const int GB = (NN + 127) / 128;
    const int SM1 = (128 * 136 + 128 * 136) * 2;  // 69632 B
    const int SM2 = (128 * 136 + 128 * 72) * 2;   // 53248 B
    cudaFuncSetAttribute((const void*)k_gemm_mma<NH1, true, float, float>,
                         cudaFuncAttributeMaxDynamicSharedMemorySize, SM1);
    cudaFuncSetAttribute((const void*)k_gemm_mma<NH2, true, __half, float>,
                         cudaFuncAttributeMaxDynamicSharedMemorySize, SM2);

    // 0: histogram (+ dtype detect)
    k_hist<<<(NE + TB - 1) / TB, TB>>>(ei);
    // 1: single-pass scan (dis + woff ready after this)
    k_scan<<<SCAN_NB, SCAN_B>>>();
    // 2: GEMM1 with dis epilogue: h1h = half(dis * (x @ half(W1)))
    {
        __half2* h1p; cudaGetSymbolAddress((void**)&h1p, g_h1h);
        k_gemm_mma<NH1, true, float, float><<<GB, 256, SM1>>>(x, W1, h1p, NN);
    }
    // 3: scatter  <-- ncu capture slot
    k_scatter<<<(NE + TB - 1) / TB, TB>>>(ei);
    // 4: agg1 (2 edges per warp-instruction)
    k_agg1<<<(NN * 32 + TB - 1) / TB, TB>>>(b1);
    // 5: GEMM2 with dis epilogue
    {
        __half* r1p;  cudaGetSymbolAddress((void**)&r1p, g_r1h);
        __half2* h2p; cudaGetSymbolAddress((void**)&h2p, g_h2h);
        k_gemm_mma<NH2, true, __half, float><<<GB, 256, SM2>>>(r1p, W2, h2p, NN);
    }
    // 6: agg2 fused with pooling (4 edges per warp-instruction)
    k_agg2_pool<<<(NN * 32 + TB - 1) / TB, TB>>>(b2, batch);
    // 7: final FC
    k_final<<<NG, 32>>>(Wfc, bfc, out);
}

// round 17
// speedup vs baseline: 1.6072x; 1.6072x over previous
#include <cuda_runtime.h>
#include <cuda_fp16.h>
#include <cstdint>

// Problem constants (fixed by the dataset)
#define NN 100000        // nodes
#define NE 3200000       // edges
#define DF 128           // input feat
#define NH1 128          // layer1 out
#define NH2 64           // layer2 out
#define NG 256           // graphs
#define NC 10            // classes

#define SCAN_B 1024
#define SCAN_NB ((NN + SCAN_B - 1) / SCAN_B)   // 98

// ---------------- scratch (static device memory; no allocation) -------------
// Invariants across calls: g_cnt == 0 on entry; g_blocksum == 0 on entry.
__device__ int   g_is64;               // 1 if indices are int64, 0 if int32
__device__ float g_dis[NN];            // deg^-1/2
__device__ int   g_cnt[NN];            // per-dst edge count
__device__ int   g_rowptr[NN + 1];     // CSR row pointers
__device__ int   g_woff[NN];           // scatter write offsets
__device__ int   g_blocksum[SCAN_NB];  // flagged block sums (value+1)
__device__ int   g_csr_src[NE];        // CSR column (src) indices
__device__ __align__(16) uint2 g_h1h[NN * 32];    // (x @ W1)*dis, fp16, 128 h/row
__device__ __align__(16) uint2 g_r1h[NN * 32];    // relu(gcn1), fp16
__device__ __align__(16) unsigned g_h2h[NN * 32]; // (r1 @ W2)*dis, fp16, 64 h/row
__device__ float g_pool[NG * NH2];     // graph sums
__device__ float g_pcnt[NG];           // graph node counts

// index load helper: p holds either int32 or int64 elements
__device__ __forceinline__ int ld_idx(const void* p, long long i, int is64) {
    if (is64) return (int)((const long long*)p)[i];
    return ((const int*)p)[i];
}

// ---------------- hist (+ dtype detect) ----------------------------------------

__global__ void k_hist(const void* __restrict__ ei) {
    __shared__ int nz;
    if (threadIdx.x == 0) nz = 0;
    __syncthreads();
    if (threadIdx.x < 256) {
        if (((const int*)ei)[2 * threadIdx.x + 1] != 0) atomicOr(&nz, 1);
    }
    __syncthreads();
    int is64 = (nz == 0);
    if (blockIdx.x == 0 && threadIdx.x == 0) g_is64 = is64;
    int e = blockIdx.x * blockDim.x + threadIdx.x;
    if (e < NE) {
        int d = ld_idx(ei, (long long)NE + e, is64);
        atomicAdd(&g_cnt[d], 1);
    }
}

// ---------------- single-pass scan (decoupled lookback, warp-shfl based) --------
__global__ void k_scan() {
    __shared__ int wsum[32];
    __shared__ int pre[SCAN_NB];
    int t = threadIdx.x, b = blockIdx.x;
    int lane = t & 31, wid = t >> 5;
    int i = b * SCAN_B + t;
    int v = 0;
    if (i < NN) {
        v = g_cnt[i];
        g_cnt[i] = 0;                       // re-establish invariant for next call
        g_dis[i] = rsqrtf((float)v + 1.0f);
    }
    // warp inclusive scan (shfl, barrier-free)
    int x = v;
    #pragma unroll
    for (int off = 1; off < 32; off <<= 1) {
        int y = __shfl_up_sync(0xffffffffu, x, off);
        if (lane >= off) x += y;
    }
    if (lane == 31) wsum[wid] = x;
    __syncthreads();
    // warp 0 scans the 32 warp sums
    if (wid == 0) {
        int w = wsum[lane];
        #pragma unroll
        for (int off = 1; off < 32; off <<= 1) {
            int y = __shfl_up_sync(0xffffffffu, w, off);
            if (lane >= off) w += y;
        }
        wsum[lane] = w;
    }
    __syncthreads();
    int incl = x + (wid > 0 ? wsum[wid - 1] : 0);
    if (t == SCAN_B - 1) {
        __threadfence();
        atomicExch(&g_blocksum[b], incl + 1);
    }
    if (b == 0) {
        for (int j = t; j < NG * NH2; j += SCAN_B) g_pool[j] = 0.f;
        if (t < NG) g_pcnt[t] = 0.f;
    }
    if (t < b) {
        volatile int* bs = g_blocksum;
        int xv;
        do { xv = bs[t]; } while (xv == 0);
        pre[t] = xv - 1;
    }
    __syncthreads();
    __shared__ int prefix;
    if (t == 0) {
        int p = 0;
        for (int j = 0; j < b; j++) p += pre[j];
        prefix = p;
    }
    __syncthreads();
    if (i < NN) {
        int excl = prefix + incl - v;
        g_rowptr[i] = excl;
        g_woff[i] = excl;
    }
    if (i == 0) g_rowptr[NN] = NE;
}

// ---------------- scatter -------------------------------------------------------

__global__ void k_scatter(const void* __restrict__ ei) {
    if (blockIdx.x == 0 && threadIdx.x < SCAN_NB) g_blocksum[threadIdx.x] = 0;
    int e = blockIdx.x * blockDim.x + threadIdx.x;
    int is64 = g_is64;
    if (e < NE) {
        int s = ld_idx(ei, e, is64);
        int d = ld_idx(ei, (long long)NE + e, is64);
        int pos = atomicAdd(&g_woff[d], 1);
        g_csr_src[pos] = s;
    }
}

// ---------------- tensor-core GEMM (mma.sync m16n8k16 fp16 -> fp32) ----------
// Optional epilogue scale: C[row,:] *= g_dis[row]  (folds GCN norm into features)
__device__ __forceinline__ uint4 cvt8(const float* p) {
    const float4* s = (const float4*)p;
    float4 f0 = s[0], f1 = s[1];
    uint4 v;
    *(__half2*)&v.x = __floats2half2_rn(f0.x, f0.y);
    *(__half2*)&v.y = __floats2half2_rn(f0.z, f0.w);
    *(__half2*)&v.z = __floats2half2_rn(f1.x, f1.y);
    *(__half2*)&v.w = __floats2half2_rn(f1.z, f1.w);
    return v;
}
__device__ __forceinline__ uint4 ld_chunk(const __half* A, long long row, int ch) {
    return ((const uint4*)A)[row * 16 + ch];
}
__device__ __forceinline__ uint4 ld_chunk(const float* A, long long row, int ch) {
    return cvt8(&A[row * 128 + ch * 8]);
}
__device__ __forceinline__ uint4 ld_wchunk(const __half* W, int c) {
    return ((const uint4*)W)[c];
}
__device__ __forceinline__ uint4 ld_wchunk(const float* W, int c) {
    return cvt8(&W[c * 8]);
}

template <int NOUT, bool SCALE, typename AT, typename WT>
__global__ void k_gemm_mma(const AT* __restrict__ A, const WT* __restrict__ W,
                           __half2* __restrict__ C, int M) {
    constexpr int K = 128;
    constexpr int AST = 136;
    constexpr int WST = NOUT + 8;
    extern __shared__ __half sm[];
    __half* As = sm;
    __half* Ws = sm + 128 * AST;
    int tid = threadIdx.x;
    int wid = tid >> 5, lane = tid & 31;
    int rb = blockIdx.x * 128;

    #pragma unroll
    for (int i = 0; i < 8; i++) {
        int c = tid + i * 256;
        int row = c >> 4, ch = c & 15;
        int gr = rb + row;
        uint4 v = make_uint4(0u, 0u, 0u, 0u);
        if (gr < M) v = ld_chunk(A, (long long)gr, ch);
        *(uint4*)&As[row * AST + ch * 8] = v;
    }
    {
        constexpr int NCH = K * NOUT / 8;
        #pragma unroll
        for (int c = tid; c < NCH; c += 256) {
            int row = c / (NOUT / 8), col = c % (NOUT / 8);
            *(uint4*)&Ws[row * WST + col * 8] = ld_wchunk(W, c);
        }
    }
    __syncthreads();

    constexpr int NT = NOUT / 8;
    float acc[NT][4];
    #pragma unroll
    for (int i = 0; i < NT; i++) {
        acc[i][0] = acc[i][1] = acc[i][2] = acc[i][3] = 0.f;
    }

    uint32_t a_base = (uint32_t)__cvta_generic_to_shared(
                          &As[(wid * 16 + (lane & 15)) * AST]) + ((lane >> 4) << 4);
    uint32_t b_base = (uint32_t)__cvta_generic_to_shared(
                          &Ws[(lane & 15) * WST]) + ((lane >> 4) << 4);

    #pragma unroll
    for (int kk = 0; kk < K / 16; kk++) {
        uint32_t a0, a1, a2, a3;
        asm volatile("ldmatrix.sync.aligned.m8n8.x4.shared.b16 {%0,%1,%2,%3}, [%4];"
                     : "=r"(a0), "=r"(a1), "=r"(a2), "=r"(a3)
                     : "r"(a_base + kk * 32));
        uint32_t brow = b_base + kk * 16 * (WST * 2);
        #pragma unroll
        for (int n2 = 0; n2 < NOUT / 16; n2++) {
            uint32_t b0, b1, b2, b3;
            asm volatile("ldmatrix.sync.aligned.m8n8.x4.trans.shared.b16 {%0,%1,%2,%3}, [%4];"
                         : "=r"(b0), "=r"(b1), "=r"(b2), "=r"(b3)
                         : "r"(brow + n2 * 32));
            asm volatile("mma.sync.aligned.m16n8k16.row.col.f32.f16.f16.f32 "
                         "{%0,%1,%2,%3}, {%4,%5,%6,%7}, {%8,%9}, {%0,%1,%2,%3};"
                         : "+f"(acc[2*n2][0]), "+f"(acc[2*n2][1]),
                           "+f"(acc[2*n2][2]), "+f"(acc[2*n2][3])
                         : "r"(a0), "r"(a1), "r"(a2), "r"(a3), "r"(b0), "r"(b1));
            asm volatile("mma.sync.aligned.m16n8k16.row.col.f32.f16.f16.f32 "
                         "{%0,%1,%2,%3}, {%4,%5,%6,%7}, {%8,%9}, {%0,%1,%2,%3};"
                         : "+f"(acc[2*n2+1][0]), "+f"(acc[2*n2+1][1]),
                           "+f"(acc[2*n2+1][2]), "+f"(acc[2*n2+1][3])
                         : "r"(a0), "r"(a1), "r"(a2), "r"(a3), "r"(b2), "r"(b3));
        }
    }

    int r0 = rb + wid * 16 + (lane >> 2);
    int cq = lane & 3;
    bool w0 = r0 < M, w1 = (r0 + 8) < M;
    float sc0 = 1.f, sc1 = 1.f;
    if (SCALE) {
        if (w0) sc0 = g_dis[r0];
        if (w1) sc1 = g_dis[r0 + 8];
    }
    #pragma unroll
    for (int nt = 0; nt < NT; nt++) {
        if (w0) C[(long long)r0 * (NOUT/2) + nt * 4 + cq] =
                    __floats2half2_rn(acc[nt][0] * sc0, acc[nt][1] * sc0);
        if (w1) C[(long long)(r0 + 8) * (NOUT/2) + nt * 4 + cq] =
                    __floats2half2_rn(acc[nt][2] * sc1, acc[nt][3] * sc1);
    }
}

// ---------------- aggregation kernels (R15-best forms) --------------------------
// Warp-per-node, weight-free gathers, grouped fp16 accumulation (flush every 8).

__global__ void k_agg1(const float* __restrict__ b1) {
    int gw   = (blockIdx.x * blockDim.x + threadIdx.x) >> 5;
    int lane = threadIdx.x & 31;
    if (gw >= NN) return;
    int d = gw;
    int s0 = g_rowptr[d], s1 = g_rowptr[d + 1];
    float4 acc = make_float4(0.f, 0.f, 0.f, 0.f);
    const __half2 hz = __float2half2_rn(0.f);
    for (int j0 = s0; j0 < s1; j0 += 32) {
        int jj = j0 + lane;
        int s_l = (jj < s1) ? g_csr_src[jj] : 0;
        int m = min(32, s1 - j0);
        int k = 0;
        while (k < m) {
            int kend = min(k + 8, m);
            __half2 h0 = hz, h1 = hz;
            for (; k < kend; k++) {
                int s = __shfl_sync(0xffffffffu, s_l, k);
                uint2 raw = g_h1h[s * 32 + lane];
                h0 = __hadd2(h0, *(__half2*)&raw.x);
                h1 = __hadd2(h1, *(__half2*)&raw.y);
            }
            float2 f0 = __half22float2(h0);
            float2 f1 = __half22float2(h1);
            acc.x += f0.x; acc.y += f0.y;
            acc.z += f1.x; acc.w += f1.y;
        }
    }
    float dd = g_dis[d];
    uint2 hraw = g_h1h[d * 32 + lane];              // self row (already *dis)
    float2 ha = __half22float2(*(__half2*)&hraw.x);
    float2 hb = __half22float2(*(__half2*)&hraw.y);
    float4 bv = ((const float4*)b1)[lane];
    float ox = fmaxf(dd * (acc.x + ha.x) + bv.x, 0.f);
    float oy = fmaxf(dd * (acc.y + ha.y) + bv.y, 0.f);
    float oz = fmaxf(dd * (acc.z + hb.x) + bv.z, 0.f);
    float ow = fmaxf(dd * (acc.w + hb.y) + bv.w, 0.f);
    uint2 o;
    *(__half2*)&o.x = __floats2half2_rn(ox, oy);
    *(__half2*)&o.y = __floats2half2_rn(oz, ow);
    g_r1h[d * 32 + lane] = o;
}

__global__ void k_agg2_pool(const float* __restrict__ b2,
                            const void* __restrict__ batch) {
    int gw   = (blockIdx.x * blockDim.x + threadIdx.x) >> 5;
    int lane = threadIdx.x & 31;
    if (gw >= NN) return;
    int is64 = g_is64;
    int d = gw;
    int s0 = g_rowptr[d], s1 = g_rowptr[d + 1];
    float2 acc = make_float2(0.f, 0.f);
    const __half2 hz = __float2half2_rn(0.f);
    for (int j0 = s0; j0 < s1; j0 += 32) {
        int jj = j0 + lane;
        int s_l = (jj < s1) ? g_csr_src[jj] : 0;
        int m = min(32, s1 - j0);
        int k = 0;
        while (k < m) {
            int kend = min(k + 8, m);
            __half2 h0 = hz;
            for (; k < kend; k++) {
                int s = __shfl_sync(0xffffffffu, s_l, k);
                unsigned raw = g_h2h[s * 32 + lane];
                h0 = __hadd2(h0, *(__half2*)&raw);
            }
            float2 f0 = __half22float2(h0);
            acc.x += f0.x; acc.y += f0.y;
        }
    }
    float dd = g_dis[d];
    unsigned hraw = g_h2h[d * 32 + lane];           // self row (already *dis)
    float2 hv = __half22float2(*(__half2*)&hraw);
    float2 bv = ((const float2*)b2)[lane];
    float ox = dd * (acc.x + hv.x) + bv.x;
    float oy = dd * (acc.y + hv.y) + bv.y;
    int g = ld_idx(batch, d, is64);
    atomicAdd(&g_pool[g * NH2 + lane * 2 + 0], ox);
    atomicAdd(&g_pool[g * NH2 + lane * 2 + 1], oy);
    if (lane == 0) atomicAdd(&g_pcnt[g], 1.0f);
}

__global__ void k_final(const float* __restrict__ Wfc,
                        const float* __restrict__ bfc,
                        float* __restrict__ out) {
    int g = blockIdx.x;
    int c = threadIdx.x;
    if (c >= NC) return;
    float inv = 1.0f / fmaxf(g_pcnt[g], 1.0f);
    float s = 0.f;
    #pragma unroll 8
    for (int f = 0; f < NH2; f++) {
        s += g_pool[g * NH2 + f] * Wfc[f * NC + c];
    }
    out[g * NC + c] = s * inv + bfc[c];
}

// ---------------- launch -----------------------------------------------------

extern "C" void kernel_launch(void* const* d_in, const int* in_sizes, int n_in,
                              void* d_out, int out_size) {
    const float* x     = (const float*)d_in[0];
    const void*  ei    = d_in[1];
    const void*  batch = d_in[2];
    const float* W1    = (const float*)d_in[3];
    const float* b1    = (const float*)d_in[4];
    const float* W2    = (const float*)d_in[5];
    const float* b2    = (const float*)d_in[6];
    const float* Wfc   = (const float*)d_in[7];
    const float* bfc   = (const float*)d_in[8];
    float* out = (float*)d_out;

    const int TB = 256;
    const int GB = (NN + 127) / 128;
    const int SM1 = (128 * 136 + 128 * 136) * 2;  // 69632 B
    const int SM2 = (128 * 136 + 128 * 72) * 2;   // 53248 B
    cudaFuncSetAttribute((const void*)k_gemm_mma<NH1, true, float, float>,
                         cudaFuncAttributeMaxDynamicSharedMemorySize, SM1);
    cudaFuncSetAttribute((const void*)k_gemm_mma<NH2, true, __half, float>,
                         cudaFuncAttributeMaxDynamicSharedMemorySize, SM2);

    // 0: histogram (+ dtype detect)
    k_hist<<<(NE + TB - 1) / TB, TB>>>(ei);
    // 1: single-pass scan (dis + woff ready after this)
    k_scan<<<SCAN_NB, SCAN_B>>>();
    // 2: GEMM1 with dis epilogue: h1h = half(dis * (x @ half(W1)))
    {
        __half2* h1p; cudaGetSymbolAddress((void**)&h1p, g_h1h);
        k_gemm_mma<NH1, true, float, float><<<GB, 256, SM1>>>(x, W1, h1p, NN);
    }
    // 3: scatter  <-- ncu capture slot
    k_scatter<<<(NE + TB - 1) / TB, TB>>>(ei);
    // 4: agg1 + bias + relu -> r1h (grouped fp16 accumulation)
    k_agg1<<<(NN * 32 + TB - 1) / TB, TB>>>(b1);
    // 5: GEMM2 with dis epilogue
    {
        __half* r1p;  cudaGetSymbolAddress((void**)&r1p, g_r1h);
        __half2* h2p; cudaGetSymbolAddress((void**)&h2p, g_h2h);
        k_gemm_mma<NH2, true, __half, float><<<GB, 256, SM2>>>(r1p, W2, h2p, NN);
    }
    // 6: agg2 fused with pooling (grouped fp16 accumulation)
    k_agg2_pool<<<(NN * 32 + TB - 1) / TB, TB>>>(b2, batch);
    // 7: final FC
    k_final<<<NG, 32>>>(Wfc, bfc, out);
}